// round 12
// baseline (speedup 1.0000x reference)
#include <cuda_runtime.h>
#include <cstdint>

// SpatialPool: fm [B=16, C=512, H=38, W=38] f32 (NCHW)
//   -> out [B, H*W, 9*C] f32, out[b, h*W+w, (di*3+dj)*C + c]
//      = fm[b, c, clamp(h+di-1), clamp(w+dj-1)]  (replicate pad)
//
// R12: persistent CTAs, 8 batch-tiles each, double-buffered cp.async
// (tile t+1 loads overlap tile t stores) with SMALL buffers (CSUB=64,
// 2 x 21.5KB) so occupancy stays 4 CTAs/SM. Grid = 608 CTAs = ~1 wave.
// Write phase: half-warp per 256B chunk, XOR-swizzled conflict-free LDS.

namespace {
constexpr int HH   = 38;
constexpr int C    = 512;
constexpr int CSUB = 64;          // channels per CTA
constexpr int NCG  = C / CSUB;    // 8
constexpr int NB   = 9;
constexpr int WT   = 19;
constexpr int LW   = WT + 2;      // 21
constexpr int NY   = 2;
constexpr int NR   = NY + 2;      // 4
constexpr int NPOS = NR * LW;     // 84
constexpr int THREADS = 512;
constexpr int HW   = HH * HH;     // 1444
constexpr int RS4  = NB * C / 4;  // 1152
constexpr int YS4  = HH * RS4;
constexpr int BUF  = NPOS * CSUB;       // 5376 floats = 21.5KB
constexpr int NTILE = 8;                // batches per CTA (b0 + 2k)
constexpr int CHUNKS = NY * WT * NB;    // 342 chunks (of 64 floats) per tile
}

__device__ __forceinline__ void cp_async4(float* smem_dst, const float* gsrc) {
    uint32_t sa = (uint32_t)__cvta_generic_to_shared(smem_dst);
    asm volatile("cp.async.ca.shared.global [%0], [%1], 4;\n"
                 :: "r"(sa), "l"(gsrc) : "memory");
}

__global__ __launch_bounds__(THREADS, 4)
void spatialpool_kernel(const float* __restrict__ fm, float* __restrict__ out) {
    // logical (pos, c) at buf[pos*64 + 4*((c>>2)^(pos&15)) + (c&3)]
    __shared__ float smP[2 * BUF];   // 43,008 B -> 4 CTAs/SM

    const int lane = threadIdx.x & 31;
    const int wid  = threadIdx.x >> 5;

    const int wh = blockIdx.x & 1;
    const int cg = blockIdx.x >> 1;        // channel group 0..7
    const int w0 = wh * WT;
    const int y0 = blockIdx.y * NY;
    const int b0 = blockIdx.z;             // tiles: b = b0 + 2k

    // ---- Tile-invariant load pattern: thread owns p = lane+32k,
    // sweeps c = wid + 16m (m<4). Computed ONCE, reused for 8 tiles. ----
    int goff[3], swb[3];
    int nk = 0;
    #pragma unroll
    for (int k = 0; k < 3; ++k) {
        int p = lane + 32 * k;
        if (k == 2 && p >= NPOS) break;
        int r  = p / LW;
        int l  = p - r * LW;
        int yl = min(max(y0 - 1 + r, 0), HH - 1);
        int xg = min(max(w0 - 1 + l, 0), HH - 1);
        goff[k] = yl * HH + xg;
        swb[k]  = (p << 6) + (wid & 3);     // + swizzle key pos&15 via XOR below
        nk = k + 1;
    }
    const int cq0  = wid >> 2;              // c>>2 base (m adds 4m)
    const size_t cgoff = (size_t)cg * CSUB * HW + (size_t)wid * HW;

    float4* __restrict__ out4 = (float4*)out;
    const size_t obase0 =
        ((size_t)y0 * HH + w0) * (size_t)RS4 + (size_t)cg * (CSUB / 4)
        + (lane & 15);

    // ---- Prologue: issue tile 0 ----
    {
        const float* __restrict__ fc = fm + (size_t)b0 * C * HW + cgoff;
        for (int k = 0; k < nk; ++k) {
            int p = lane + 32 * k;
            const float* __restrict__ g = fc + goff[k];
            #pragma unroll
            for (int m = 0; m < 4; ++m) {
                int sw = swb[k] + ((((cq0 + 4 * m) ^ (p & 15))) << 2);
                cp_async4(&smP[sw], g + m * 16 * HW);
            }
        }
        asm volatile("cp.async.commit_group;\n" ::: "memory");
    }

    #pragma unroll 1
    for (int t = 0; t < NTILE; ++t) {
        // Issue tile t+1 into the other buffer (its previous store finished
        // before this iteration's leading edge via the trailing barrier).
        if (t + 1 < NTILE) {
            const float* __restrict__ fc =
                fm + (size_t)(b0 + 2 * (t + 1)) * C * HW + cgoff;
            float* __restrict__ nbuf = &smP[((t + 1) & 1) * BUF];
            for (int k = 0; k < nk; ++k) {
                int p = lane + 32 * k;
                const float* __restrict__ g = fc + goff[k];
                #pragma unroll
                for (int m = 0; m < 4; ++m) {
                    int sw = swb[k] + ((((cq0 + 4 * m) ^ (p & 15))) << 2);
                    cp_async4(&nbuf[sw], g + m * 16 * HW);
                }
            }
            asm volatile("cp.async.commit_group;\n" ::: "memory");
            asm volatile("cp.async.wait_group 1;\n" ::: "memory");
        } else {
            asm volatile("cp.async.wait_group 0;\n" ::: "memory");
        }
        __syncthreads();

        // ---- Store tile t. Half-warp per 256B chunk. ----
        const float* __restrict__ buf = &smP[(t & 1) * BUF];
        const size_t tbase = (size_t)(b0 + 2 * t) * HW * RS4 + obase0;
        const int half = lane >> 4;        // 0/1: which chunk of the pair
        const int lh   = lane & 15;        // c4 within chunk

        #pragma unroll 2
        for (int u = wid; 2 * u < CHUNKS; u += THREADS / 32) {
            int ch = 2 * u + half;         // chunk id = (o*19+wl)*9+n
            int o  = (ch >= WT * NB) ? 1 : 0;
            int rm = ch - o * (WT * NB);
            int wl = rm / NB;
            int n  = rm - wl * NB;
            int di = (n >= 6) ? 2 : ((n >= 3) ? 1 : 0);
            int pos = (o + di) * LW + wl + (n - 3 * di);

            const float4 v = *(const float4*)
                &buf[(pos << 6) + ((lh ^ (pos & 15)) << 2)];
            __stcs(&out4[tbase + (size_t)o * YS4
                         + (size_t)wl * RS4 + n * (C / 4)], v);
        }
        __syncthreads();   // buf[t&1] free for tile t+2's loads
    }
}

extern "C" void kernel_launch(void* const* d_in, const int* in_sizes, int n_in,
                              void* d_out, int out_size) {
    const float* fm = (const float*)d_in[0];
    float* out = (float*)d_out;
    (void)in_sizes; (void)n_in; (void)out_size;

    dim3 grid(2 * NCG, HH / NY, 2);   // (16, 19, 2) = 608 CTAs, 8 tiles each
    spatialpool_kernel<<<grid, THREADS>>>(fm, out);
}